// round 6
// baseline (speedup 1.0000x reference)
#include <cuda_runtime.h>
#include <cuda_bf16.h>
#include <cstdint>

#define N_NODES   100000
#define DIM       128
#define NEG       5
#define LR        0.025f
#define NCE_BIAS      11.512925464970229f   // log(100000)
#define NCE_NEG_BIAS  9.9034875525361272f   // log(100000/5)
#define LUT_SIZE  1202
#define CAP       64          // bucket capacity per node (lambda=2/5; P(>64)~0)

// snap0: bf16(original W). Written by init only; read-only afterwards.
// snap1: bf16(post-positive W). init pre-fills with bf16(W); pos_apply
//        overwrites rows of touched nodes. Frozen before neg phase starts.
__device__ __nv_bfloat16 g_snap0[(size_t)N_NODES * DIM];
__device__ __nv_bfloat16 g_snap1[(size_t)N_NODES * DIM];

// per-node update buckets: entry = (other_row_idx bitcast to float, scale)
__device__ int    g_cnt_pos[N_NODES];
__device__ int    g_cnt_neg[N_NODES];
__device__ float2 g_bkt_pos[(size_t)N_NODES * CAP];
__device__ float2 g_bkt_neg[(size_t)N_NODES * CAP];

// ---------------------------------------------------------------------------
// helpers
// ---------------------------------------------------------------------------
__device__ __forceinline__ void red4(float* addr, float x, float y, float z, float w) {
    asm volatile("red.global.add.v4.f32 [%0], {%1, %2, %3, %4};"
                 :: "l"(addr), "f"(x), "f"(y), "f"(z), "f"(w)
                 : "memory");
}

__device__ __forceinline__ float lut_sigmoid(float s, const float* __restrict__ lut) {
    s = fminf(fmaxf(s, -6.0f), 6.0f);
    int idx = (int)floorf(__fdiv_rn(s + 6.01f, 0.01f));
    idx = max(0, min(idx, LUT_SIZE - 1));
    return __ldg(lut + idx);
}

__device__ __forceinline__ void unpack4(uint2 r, float f[4]) {
    float2 lo = __bfloat1622float2(*reinterpret_cast<__nv_bfloat162*>(&r.x));
    float2 hi = __bfloat1622float2(*reinterpret_cast<__nv_bfloat162*>(&r.y));
    f[0] = lo.x; f[1] = lo.y; f[2] = hi.x; f[3] = hi.y;
}

__device__ __forceinline__ uint2 pack4(float x, float y, float z, float w) {
    __nv_bfloat162 lo = __floats2bfloat162_rn(x, y);
    __nv_bfloat162 hi = __floats2bfloat162_rn(z, w);
    uint2 o;
    o.x = *reinterpret_cast<uint32_t*>(&lo);
    o.y = *reinterpret_cast<uint32_t*>(&hi);
    return o;
}

// ---------------------------------------------------------------------------
// K0: out = W (fp32); snap0 = snap1 = bf16(W); zero bucket counters.
// ---------------------------------------------------------------------------
__global__ void __launch_bounds__(256)
init_kernel(const float4* __restrict__ W, float4* __restrict__ out, int n8) {
    int i = blockIdx.x * blockDim.x + threadIdx.x;
    if (i < N_NODES) { g_cnt_pos[i] = 0; g_cnt_neg[i] = 0; }
    if (i >= n8) return;
    float4 a = __ldg(W + 2 * i);
    float4 b = __ldg(W + 2 * i + 1);
    out[2 * i]     = a;
    out[2 * i + 1] = b;
    uint2 lo = pack4(a.x, a.y, a.z, a.w);
    uint2 hi = pack4(b.x, b.y, b.z, b.w);
    uint4 o; o.x = lo.x; o.y = lo.y; o.z = hi.x; o.w = hi.y;
    reinterpret_cast<uint4*>(g_snap0)[i] = o;
    reinterpret_cast<uint4*>(g_snap1)[i] = o;
}

// ---------------------------------------------------------------------------
// K1: pos scores. One warp per pair: gather 2 rows from snap0, dot, sc;
// push one (other,sc) record into each endpoint's bucket.
// ---------------------------------------------------------------------------
__global__ void __launch_bounds__(256)
pos_score_kernel(const float* __restrict__ lut,
                 const int*   __restrict__ iu,
                 const int*   __restrict__ iv,
                 float*       __restrict__ out,   // overflow fallback only
                 int n_pairs) {
    int warp = (blockIdx.x * blockDim.x + threadIdx.x) >> 5;
    int lane = threadIdx.x & 31;
    if (warp >= n_pairs) return;

    const uint2* snap = reinterpret_cast<const uint2*>(g_snap0);
    int u = __ldg(iu + warp);
    int v = __ldg(iv + warp);

    uint2 ra = __ldg(snap + u * 32 + lane);
    uint2 rb = __ldg(snap + v * 32 + lane);
    float a[4], b[4];
    unpack4(ra, a);
    unpack4(rb, b);

    float p = a[0] * b[0] + a[1] * b[1] + a[2] * b[2] + a[3] * b[3];
#pragma unroll
    for (int o = 16; o; o >>= 1) p += __shfl_xor_sync(0xffffffffu, p, o);

    float sc = (1.0f - lut_sigmoid(p - NCE_BIAS, lut)) * LR;

    int slot_u = 0, slot_v = 0;
    if (lane == 0) slot_u = atomicAdd(&g_cnt_pos[u], 1);
    if (lane == 1) slot_v = atomicAdd(&g_cnt_pos[v], 1);
    slot_u = __shfl_sync(0xffffffffu, slot_u, 0);
    slot_v = __shfl_sync(0xffffffffu, slot_v, 1);

    if (lane == 0 && slot_u < CAP)
        g_bkt_pos[(size_t)u * CAP + slot_u] = make_float2(__int_as_float(v), sc);
    if (lane == 1 && slot_v < CAP)
        g_bkt_pos[(size_t)v * CAP + slot_v] = make_float2(__int_as_float(u), sc);
    // overflow fallback (statistically never). NOTE: such a row would miss its
    // snap1 refresh for the overflowed contribution; probability ~0 at CAP=64.
    if (slot_u >= CAP)
        red4(out + u * DIM + lane * 4, sc * b[0], sc * b[1], sc * b[2], sc * b[3]);
    if (slot_v >= CAP)
        red4(out + v * DIM + lane * 4, sc * a[0], sc * a[1], sc * a[2], sc * a[3]);
}

// ---------------------------------------------------------------------------
// K2: pos apply. One warp per node (exclusive row owner): gather partner
// rows from snap0 (frozen -> race-free), accumulate, plain RMW the fp32 row,
// write refreshed row image to snap1 (single rounding).
// ---------------------------------------------------------------------------
__global__ void __launch_bounds__(256)
pos_apply_kernel(float* __restrict__ out) {
    int node = (blockIdx.x * blockDim.x + threadIdx.x) >> 5;
    int lane = threadIdx.x & 31;
    if (node >= N_NODES) return;

    int cnt = g_cnt_pos[node];
    if (cnt == 0) return;
    cnt = min(cnt, CAP);

    const uint2* snap = reinterpret_cast<const uint2*>(g_snap0);
    float acc0 = 0.f, acc1 = 0.f, acc2 = 0.f, acc3 = 0.f;
    for (int e = 0; e < cnt; e++) {
        float2 ent = g_bkt_pos[(size_t)node * CAP + e];   // broadcast load
        int   oth = __float_as_int(ent.x);
        float sc  = ent.y;
        uint2 r = __ldg(snap + oth * 32 + lane);
        float b[4];
        unpack4(r, b);
        acc0 += sc * b[0]; acc1 += sc * b[1]; acc2 += sc * b[2]; acc3 += sc * b[3];
    }

    float4* row = reinterpret_cast<float4*>(out + node * DIM);
    float4 cur = row[lane];
    cur.x += acc0; cur.y += acc1; cur.z += acc2; cur.w += acc3;
    row[lane] = cur;
    reinterpret_cast<uint2*>(g_snap1 + node * DIM)[lane] =
        pack4(cur.x, cur.y, cur.z, cur.w);
}

// ---------------------------------------------------------------------------
// K3: neg scores. One warp per group of NEG sharing one u (gathers snap1).
// Aggregated u update -> direct red4. v updates -> bucket push.
// ---------------------------------------------------------------------------
__global__ void __launch_bounds__(256)
neg_score_kernel(const float* __restrict__ lut,
                 const int*   __restrict__ inu,
                 const int*   __restrict__ inv,
                 float*       __restrict__ out,
                 int n_groups) {
    int g    = (blockIdx.x * blockDim.x + threadIdx.x) >> 5;
    int lane = threadIdx.x & 31;
    if (g >= n_groups) return;

    const uint2* snap = reinterpret_cast<const uint2*>(g_snap1);

    int u = __ldg(inu + g * NEG);             // all NEG entries identical
    int vv[NEG];
#pragma unroll
    for (int j = 0; j < NEG; j++) vv[j] = __ldg(inv + g * NEG + j);

    uint2 ru = __ldg(snap + u * 32 + lane);
    uint2 rb[NEG];
#pragma unroll
    for (int j = 0; j < NEG; j++) rb[j] = __ldg(snap + vv[j] * 32 + lane);

    float a[4];
    unpack4(ru, a);

    float p[NEG];
#pragma unroll
    for (int j = 0; j < NEG; j++) {
        float b[4];
        unpack4(rb[j], b);
        p[j] = a[0] * b[0] + a[1] * b[1] + a[2] * b[2] + a[3] * b[3];
    }

#pragma unroll
    for (int o = 16; o; o >>= 1) {
#pragma unroll
        for (int j = 0; j < NEG; j++)
            p[j] += __shfl_xor_sync(0xffffffffu, p[j], o);
    }

    float sc[NEG];
#pragma unroll
    for (int j = 0; j < NEG; j++)
        sc[j] = -lut_sigmoid(p[j] - NCE_NEG_BIAS, lut) * LR;

    // aggregated u update (5 rows -> 1)
    float du0 = 0.f, du1 = 0.f, du2 = 0.f, du3 = 0.f;
#pragma unroll
    for (int j = 0; j < NEG; j++) {
        float b[4];
        unpack4(rb[j], b);
        du0 += sc[j] * b[0]; du1 += sc[j] * b[1];
        du2 += sc[j] * b[2]; du3 += sc[j] * b[3];
    }
    red4(out + u * DIM + lane * 4, du0, du1, du2, du3);

    // push v records (lane j handles negative j)
    int slot = 0;
    if (lane < NEG) slot = atomicAdd(&g_cnt_neg[vv[lane]], 1);
    if (lane < NEG && slot < CAP)
        g_bkt_neg[(size_t)vv[lane] * CAP + slot] =
            make_float2(__int_as_float(u), sc[lane]);
    // overflow fallback (statistically never)
#pragma unroll
    for (int j = 0; j < NEG; j++) {
        int s = __shfl_sync(0xffffffffu, slot, j);
        if (s >= CAP)
            red4(out + vv[j] * DIM + lane * 4,
                 sc[j] * a[0], sc[j] * a[1], sc[j] * a[2], sc[j] * a[3]);
    }
}

// ---------------------------------------------------------------------------
// K4: neg apply. One warp per node: gather u-rows from snap1 (frozen),
// accumulate, plain RMW the fp32 output row.
// ---------------------------------------------------------------------------
__global__ void __launch_bounds__(256)
neg_apply_kernel(float* __restrict__ out) {
    int node = (blockIdx.x * blockDim.x + threadIdx.x) >> 5;
    int lane = threadIdx.x & 31;
    if (node >= N_NODES) return;

    int cnt = g_cnt_neg[node];
    if (cnt == 0) return;
    cnt = min(cnt, CAP);

    const uint2* snap = reinterpret_cast<const uint2*>(g_snap1);
    float acc0 = 0.f, acc1 = 0.f, acc2 = 0.f, acc3 = 0.f;
    for (int e = 0; e < cnt; e++) {
        float2 ent = g_bkt_neg[(size_t)node * CAP + e];
        int   oth = __float_as_int(ent.x);
        float sc  = ent.y;
        uint2 r = __ldg(snap + oth * 32 + lane);
        float b[4];
        unpack4(r, b);
        acc0 += sc * b[0]; acc1 += sc * b[1]; acc2 += sc * b[2]; acc3 += sc * b[3];
    }

    float4* row = reinterpret_cast<float4*>(out + node * DIM);
    float4 cur = row[lane];
    cur.x += acc0; cur.y += acc1; cur.z += acc2; cur.w += acc3;
    row[lane] = cur;
}

// ---------------------------------------------------------------------------
// launch
// ---------------------------------------------------------------------------
extern "C" void kernel_launch(void* const* d_in, const int* in_sizes, int n_in,
                              void* d_out, int out_size) {
    const float* W    = (const float*)d_in[0];
    const float* lut  = (const float*)d_in[1];
    const int*   ipu  = (const int*)d_in[2];
    const int*   ipv  = (const int*)d_in[3];
    const int*   inu  = (const int*)d_in[4];
    const int*   inv  = (const int*)d_in[5];
    float*       out  = (float*)d_out;

    const int n_pos   = in_sizes[2];          // 100000
    const int n_neg   = in_sizes[4];          // 500000
    const int n_group = n_neg / NEG;          // 100000
    const int n8      = out_size / 8;         // 1,600,000

    const int CT = 256;
    const int node_blocks = (N_NODES * 32 + CT - 1) / CT;

    init_kernel<<<(n8 + CT - 1) / CT, CT>>>((const float4*)W, (float4*)out, n8);
    pos_score_kernel<<<(n_pos * 32 + CT - 1) / CT, CT>>>(lut, ipu, ipv, out, n_pos);
    pos_apply_kernel<<<node_blocks, CT>>>(out);
    neg_score_kernel<<<(n_group * 32 + CT - 1) / CT, CT>>>(lut, inu, inv, out, n_group);
    neg_apply_kernel<<<node_blocks, CT>>>(out);
}

// round 7
// speedup vs baseline: 1.4943x; 1.4943x over previous
#include <cuda_runtime.h>
#include <cuda_bf16.h>
#include <cstdint>

#define N_NODES   100000
#define DIM       128
#define NEG       5
#define LR        0.025f
#define NCE_BIAS      11.512925464970229f   // log(100000)
#define NCE_NEG_BIAS  9.9034875525361272f   // log(100000/5)
#define LUT_SIZE  1202

// bf16 gather table. Phase 1 (pos): bf16(original W). Phase 2 (neg):
// rewritten to bf16(post-positive table) by snapshot_kernel.
__device__ __nv_bfloat16 g_snap[(size_t)N_NODES * DIM];

// ---------------------------------------------------------------------------
// helpers
// ---------------------------------------------------------------------------
__device__ __forceinline__ void red4(float* addr, float x, float y, float z, float w) {
    asm volatile("red.global.add.v4.f32 [%0], {%1, %2, %3, %4};"
                 :: "l"(addr), "f"(x), "f"(y), "f"(z), "f"(w)
                 : "memory");
}

__device__ __forceinline__ float lut_sigmoid(float s, const float* __restrict__ lut) {
    // clamp to [-6,6] is semantically required (scores usually < -6; the
    // reference clips BEFORE binning, landing in bin 1, not bin 0).
    s = fminf(fmaxf(s, -6.0f), 6.0f);
    int idx = __float2int_rd((s + 6.01f) * 100.0f);   // FMUL + F2I.RD
    idx = max(0, min(idx, LUT_SIZE - 1));
    return __ldg(lut + idx);
}

__device__ __forceinline__ void unpack4(uint2 r, float f[4]) {
    float2 lo = __bfloat1622float2(*reinterpret_cast<__nv_bfloat162*>(&r.x));
    float2 hi = __bfloat1622float2(*reinterpret_cast<__nv_bfloat162*>(&r.y));
    f[0] = lo.x; f[1] = lo.y; f[2] = hi.x; f[3] = hi.y;
}

__device__ __forceinline__ uint4 pack8(float4 a, float4 b) {
    __nv_bfloat162 p0 = __floats2bfloat162_rn(a.x, a.y);
    __nv_bfloat162 p1 = __floats2bfloat162_rn(a.z, a.w);
    __nv_bfloat162 p2 = __floats2bfloat162_rn(b.x, b.y);
    __nv_bfloat162 p3 = __floats2bfloat162_rn(b.z, b.w);
    uint4 o;
    o.x = *reinterpret_cast<uint32_t*>(&p0);
    o.y = *reinterpret_cast<uint32_t*>(&p1);
    o.z = *reinterpret_cast<uint32_t*>(&p2);
    o.w = *reinterpret_cast<uint32_t*>(&p3);
    return o;
}

// ---------------------------------------------------------------------------
// K0: out = W (fp32) + g_snap = bf16(W). 16 floats/thread for MLP.
// ---------------------------------------------------------------------------
__global__ void __launch_bounds__(256)
init_kernel(const float4* __restrict__ W, float4* __restrict__ out, int n16) {
    int i = blockIdx.x * blockDim.x + threadIdx.x;
    if (i >= n16) return;
    float4 a = __ldg(W + 4 * i);
    float4 b = __ldg(W + 4 * i + 1);
    float4 c = __ldg(W + 4 * i + 2);
    float4 d = __ldg(W + 4 * i + 3);
    out[4 * i]     = a;
    out[4 * i + 1] = b;
    out[4 * i + 2] = c;
    out[4 * i + 3] = d;
    reinterpret_cast<uint4*>(g_snap)[2 * i]     = pack8(a, b);
    reinterpret_cast<uint4*>(g_snap)[2 * i + 1] = pack8(c, d);
}

// K2: g_snap = bf16(out) (post-positive table), 16 floats/thread
__global__ void __launch_bounds__(256)
snapshot_kernel(const float4* __restrict__ src, int n16) {
    int i = blockIdx.x * blockDim.x + threadIdx.x;
    if (i >= n16) return;
    float4 a = __ldg(src + 4 * i);
    float4 b = __ldg(src + 4 * i + 1);
    float4 c = __ldg(src + 4 * i + 2);
    float4 d = __ldg(src + 4 * i + 3);
    reinterpret_cast<uint4*>(g_snap)[2 * i]     = pack8(a, b);
    reinterpret_cast<uint4*>(g_snap)[2 * i + 1] = pack8(c, d);
}

// ---------------------------------------------------------------------------
// K1: positives. One warp per pair; gathers bf16(W) from g_snap; red4 -> out.
// ---------------------------------------------------------------------------
__global__ void __launch_bounds__(256, 8)
pos_kernel(const float* __restrict__ lut,
           const int*   __restrict__ iu,
           const int*   __restrict__ iv,
           float*       __restrict__ out,
           int n_pairs) {
    int warp = (blockIdx.x * blockDim.x + threadIdx.x) >> 5;
    int lane = threadIdx.x & 31;
    if (warp >= n_pairs) return;

    const uint2* snap = reinterpret_cast<const uint2*>(g_snap);
    int u = __ldg(iu + warp);
    int v = __ldg(iv + warp);

    uint2 ra = __ldg(snap + u * 32 + lane);
    uint2 rb = __ldg(snap + v * 32 + lane);

    float a[4], b[4];
    unpack4(ra, a);
    unpack4(rb, b);

    float p = a[0] * b[0] + a[1] * b[1] + a[2] * b[2] + a[3] * b[3];
#pragma unroll
    for (int o = 16; o; o >>= 1) p += __shfl_xor_sync(0xffffffffu, p, o);

    float sc = (1.0f - lut_sigmoid(p - NCE_BIAS, lut)) * LR;

    red4(out + u * DIM + lane * 4, sc * b[0], sc * b[1], sc * b[2], sc * b[3]);
    red4(out + v * DIM + lane * 4, sc * a[0], sc * a[1], sc * a[2], sc * a[3]);
}

// ---------------------------------------------------------------------------
// K3: negatives. One warp per group of NEG sharing one u; aggregated u-row
// update in registers (6 red4-rows per group instead of 10).
// launch_bounds(256,6) caps regs at 40 -> 75% occupancy (was 48 regs / 54%).
// ---------------------------------------------------------------------------
__global__ void __launch_bounds__(256, 6)
neg_kernel(const float* __restrict__ lut,
           const int*   __restrict__ inu,
           const int*   __restrict__ inv,
           float*       __restrict__ out,
           int n_groups) {
    int g    = (blockIdx.x * blockDim.x + threadIdx.x) >> 5;
    int lane = threadIdx.x & 31;
    if (g >= n_groups) return;

    const uint2* snap = reinterpret_cast<const uint2*>(g_snap);

    int u = __ldg(inu + g * NEG);             // all NEG entries identical
    int vv[NEG];
#pragma unroll
    for (int j = 0; j < NEG; j++) vv[j] = __ldg(inv + g * NEG + j);

    // issue all 6 gathers before any dependent math (max MLP)
    uint2 ru = __ldg(snap + u * 32 + lane);
    uint2 rb[NEG];
#pragma unroll
    for (int j = 0; j < NEG; j++) rb[j] = __ldg(snap + vv[j] * 32 + lane);

    float a[4];
    unpack4(ru, a);

    float p[NEG];
#pragma unroll
    for (int j = 0; j < NEG; j++) {
        float b[4];
        unpack4(rb[j], b);
        p[j] = a[0] * b[0] + a[1] * b[1] + a[2] * b[2] + a[3] * b[3];
    }

    // 5 interleaved butterflies (independent chains)
#pragma unroll
    for (int o = 16; o; o >>= 1) {
#pragma unroll
        for (int j = 0; j < NEG; j++)
            p[j] += __shfl_xor_sync(0xffffffffu, p[j], o);
    }

#pragma unroll
    for (int j = 0; j < NEG; j++)
        p[j] = -lut_sigmoid(p[j] - NCE_NEG_BIAS, lut) * LR;   // p[] now = sc[]

    float du0 = 0.f, du1 = 0.f, du2 = 0.f, du3 = 0.f;
#pragma unroll
    for (int j = 0; j < NEG; j++) {
        float b[4];
        unpack4(rb[j], b);
        du0 += p[j] * b[0]; du1 += p[j] * b[1];
        du2 += p[j] * b[2]; du3 += p[j] * b[3];
        red4(out + vv[j] * DIM + lane * 4,
             p[j] * a[0], p[j] * a[1], p[j] * a[2], p[j] * a[3]);
    }
    red4(out + u * DIM + lane * 4, du0, du1, du2, du3);
}

// ---------------------------------------------------------------------------
// launch
// ---------------------------------------------------------------------------
extern "C" void kernel_launch(void* const* d_in, const int* in_sizes, int n_in,
                              void* d_out, int out_size) {
    const float* W    = (const float*)d_in[0];
    const float* lut  = (const float*)d_in[1];
    const int*   ipu  = (const int*)d_in[2];
    const int*   ipv  = (const int*)d_in[3];
    const int*   inu  = (const int*)d_in[4];
    const int*   inv  = (const int*)d_in[5];
    float*       out  = (float*)d_out;

    const int n_pos   = in_sizes[2];          // 100000
    const int n_neg   = in_sizes[4];          // 500000
    const int n_group = n_neg / NEG;          // 100000
    const int n16     = out_size / 16;        // 800,000

    const int CT = 256;

    init_kernel<<<(n16 + CT - 1) / CT, CT>>>((const float4*)W, (float4*)out, n16);
    pos_kernel<<<(n_pos * 32 + CT - 1) / CT, CT>>>(lut, ipu, ipv, out, n_pos);
    snapshot_kernel<<<(n16 + CT - 1) / CT, CT>>>((const float4*)out, n16);
    neg_kernel<<<(n_group * 32 + CT - 1) / CT, CT>>>(lut, inu, inv, out, n_group);
}